// round 7
// baseline (speedup 1.0000x reference)
#include <cuda_runtime.h>
#include <cstdint>

// ---------------------------------------------------------------------------
// Problem constants
// ---------------------------------------------------------------------------
constexpr int BB = 32, CC = 256, HH = 56, WW = 56;
constexpr int HP = 58, WP = 58;                 // padded spatial
constexpr int HWs = HH * WW;                    // 3136
constexpr int CHW = CC * HWs;                   // 802816
constexpr int PIX = BB * HWs;                   // 100352
constexpr int KW  = 72;                         // K in 32-bit words (2304 bits)
constexpr int KBITS = 2304;
constexpr float BN_EPS = 1e-5f;

constexpr int TM = 64;                          // CTA pixel tile
constexpr int TN = 128;                         // CTA cout tile
constexpr int NT_M = PIX / TM;                  // 1568
// smem: W tile [72][128] words + X tile [72][64] words
constexpr int SW_WORDS = KW * TN;               // 9216
constexpr int SX_WORDS = KW * TM;               // 4608
constexpr int SMEM_DYN = (SW_WORDS + SX_WORDS) * 4;   // 55296 B

// ---------------------------------------------------------------------------
// Device scratch (allocation-free: __device__ globals)
// ---------------------------------------------------------------------------
__device__ uint32_t g_xp[(size_t)BB * HP * WP * 8];   // packed x, padded NHWC, 3.4MB
__device__ uint32_t g_wpT[KW * CC];                   // packed w, [k][cout]
__device__ int      g_corr[9 * CC];                   // border corrections
__device__ short    g_y16[(size_t)PIX * CC];          // conv result, NCHW int16, 51MB
__device__ float    g_scale[CC];
__device__ unsigned long long g_isum[CC];
__device__ unsigned long long g_isumsq[CC];
__device__ float    g_ab[2 * CC];
__device__ int      g_one = 1;                        // opaque 1: keeps IMAD on fma pipe

// fma-pipe accumulate: acc += p * one  (IMAD, not IADD3 on the alu pipe)
__device__ __forceinline__ void acc_mad(int& acc, int p, int one) {
    asm("mad.lo.s32 %0, %1, %2, %0;" : "+r"(acc) : "r"(p), "r"(one));
}

// ---------------------------------------------------------------------------
// Kernel: weight prep — scale, packed bits [k][o], border-correction table,
// and zero the integer BN accumulators.
// ---------------------------------------------------------------------------
__global__ void wprep_kernel(const float* __restrict__ w) {
    int o = blockIdx.x, tid = threadIdx.x;
    int lane = tid & 31, warp = tid >> 5;
    const float* wp = w + ((size_t)o * CC + tid) * 9;
    float v[9]; float s = 0.0f;
#pragma unroll
    for (int t = 0; t < 9; t++) { v[t] = wp[t]; s += fabsf(v[t]); }
#pragma unroll
    for (int off = 16; off; off >>= 1) s += __shfl_xor_sync(~0u, s, off);
    __shared__ float sh[8];
    __shared__ uint32_t words[9][8];
    __shared__ int S[9];
    if (lane == 0) sh[warp] = s;

    // pack: warp j supplies bits for channels j*32+lane, word index tap*8+j
#pragma unroll
    for (int t = 0; t < 9; t++) {
        uint32_t m = __ballot_sync(~0u, v[t] > 0.0f);
        if (lane == 0) words[t][warp] = m;
    }
    __syncthreads();
    if (tid == 0) {
        float tot = 0.0f;
        for (int i = 0; i < 8; i++) tot += sh[i];
        g_scale[o] = tot / (float)KBITS;
        g_isum[o] = 0ull; g_isumsq[o] = 0ull;
    }
    if (tid < 72) {
        int t = tid >> 3, j = tid & 7;
        g_wpT[(t * 8 + j) * CC + o] = words[t][j];
    }
    if (tid < 9) {
        int P = 0;
        for (int j = 0; j < 8; j++) P += __popc(words[tid][j]);
        S[tid] = 2 * P - 256;          // sum_ci sign(w[o][ci][tap])
    }
    __syncthreads();
    if (tid < 9) {                      // tid = border category ht*3+wt
        int ht = tid / 3, wt = tid % 3;
        int corr = 0;
        for (int kh = 0; kh < 3; kh++)
            for (int kw = 0; kw < 3; kw++) {
                bool miss = (ht == 0 && kh == 0) || (ht == 2 && kh == 2) ||
                            (wt == 0 && kw == 0) || (wt == 2 && kw == 2);
                if (miss) corr += S[kh * 3 + kw];
            }
        g_corr[tid * CC + o] = corr;
    }
}

// ---------------------------------------------------------------------------
// Kernel: zero packed-x buffer (pad ring stays 0 = "all -1", corrected later)
// ---------------------------------------------------------------------------
__global__ void zero_xp_kernel() {
    size_t i = (size_t)blockIdx.x * 256 + threadIdx.x;   // 215296 uint4
    ((uint4*)g_xp)[i] = make_uint4(0, 0, 0, 0);
}

// ---------------------------------------------------------------------------
// Kernel: pack sign bits of x: NCHW fp32 -> padded [b][h][w][8 words]
// warp j produces word j (channels j*32+lane), matching wprep's convention.
// ---------------------------------------------------------------------------
__global__ void xpack_kernel(const float* __restrict__ x) {
    int h = blockIdx.x, b = blockIdx.y;
    int lane = threadIdx.x & 31, warp = threadIdx.x >> 5;
    const float4* xrow =
        (const float4*)(x + (((size_t)(b * CC + warp * 32 + lane)) * HH + h) * WW);
    uint32_t* base = &g_xp[(((size_t)(b * HP + h + 1)) * WP + 1) * 8 + warp];
    for (int w0 = 0; w0 < WW; w0 += 4) {
        float4 v = xrow[w0 >> 2];
        uint32_t m0 = __ballot_sync(~0u, v.x > 0.0f);
        uint32_t m1 = __ballot_sync(~0u, v.y > 0.0f);
        uint32_t m2 = __ballot_sync(~0u, v.z > 0.0f);
        uint32_t m3 = __ballot_sync(~0u, v.w > 0.0f);
        if (lane == 0) {
            base[(w0 + 0) * 8] = m0; base[(w0 + 1) * 8] = m1;
            base[(w0 + 2) * 8] = m2; base[(w0 + 3) * 8] = m3;
        }
    }
}

// ---------------------------------------------------------------------------
// Kernel: XNOR-popcount implicit-GEMM conv + fused exact BN stats.
// CTA: 64 pixels x 128 couts. Thread: 4 pixels x 8 couts. K resident in smem.
// ALU pipe carries only XOR+POPC; accumulation rides the fma pipe via IMAD.
// ---------------------------------------------------------------------------
__global__ __launch_bounds__(256, 3) void gemm_kernel() {
    extern __shared__ uint32_t smem[];
    uint32_t* sW = smem;                // [72][128]
    uint32_t* sX = smem + SW_WORDS;     // [72][64]

    const int tid = threadIdx.x;
    const int lane = tid & 31;
    const int p0 = blockIdx.x * TM;
    const int n0 = blockIdx.y * TN;
    const int one = g_one;              // opaque 1 (forces IMAD accumulate)

    // ---- load W tile (coalesced) ----
    {
        int col = tid & 127, khalf = tid >> 7;
        for (int k = khalf; k < KW; k += 2)
            sW[k * TN + col] = g_wpT[k * CC + n0 + col];
    }
    // ---- gather X tile: 64 pixels x 9 taps x 8 words ----
    for (int idx = tid; idx < 576; idx += 256) {
        int pix = idx & 63, tap = idx >> 6;
        int p = p0 + pix;
        int b = p / HWs, hw = p - b * HWs;
        int h = hw / WW, w = hw - h * WW;
        int kh = tap / 3, kw = tap - 3 * kh;
        const uint4* src =
            (const uint4*)&g_xp[(((size_t)(b * HP + h + kh)) * WP + (w + kw)) * 8];
        uint4 q0 = src[0], q1 = src[1];
        int kb = tap * 8;
        sX[(kb + 0) * TM + pix] = q0.x; sX[(kb + 1) * TM + pix] = q0.y;
        sX[(kb + 2) * TM + pix] = q0.z; sX[(kb + 3) * TM + pix] = q0.w;
        sX[(kb + 4) * TM + pix] = q1.x; sX[(kb + 5) * TM + pix] = q1.y;
        sX[(kb + 6) * TM + pix] = q1.z; sX[(kb + 7) * TM + pix] = q1.w;
    }
    __syncthreads();

    const int pg = tid & 15;    // pixel group: pixels pg*4..+3
    const int cg = tid >> 4;    // cout group:  couts cg*8..+7
    const uint4* sXv = (const uint4*)sX;   // row k: 16 uint4
    const uint4* sWv = (const uint4*)sW;   // row k: 32 uint4

    int acc[4][8];
#pragma unroll
    for (int i = 0; i < 4; i++)
#pragma unroll
        for (int j = 0; j < 8; j++) acc[i][j] = 0;

    for (int k = 0; k < KW; k += 4) {
        uint32_t xs[4][4];
#pragma unroll
        for (int kk = 0; kk < 4; kk++) {
            uint4 q = sXv[(k + kk) * 16 + pg];
            xs[kk][0] = q.x; xs[kk][1] = q.y; xs[kk][2] = q.z; xs[kk][3] = q.w;
        }
#pragma unroll
        for (int kk = 0; kk < 4; kk++) {
            // couts 0..3
            {
                uint4 wq = sWv[(k + kk) * 32 + cg * 2];
                uint32_t ws[4] = {wq.x, wq.y, wq.z, wq.w};
#pragma unroll
                for (int i = 0; i < 4; i++)
#pragma unroll
                    for (int j = 0; j < 4; j++)
                        acc_mad(acc[i][j], __popc(xs[kk][i] ^ ws[j]), one);
            }
            // couts 4..7
            {
                uint4 wq = sWv[(k + kk) * 32 + cg * 2 + 1];
                uint32_t ws[4] = {wq.x, wq.y, wq.z, wq.w};
#pragma unroll
                for (int i = 0; i < 4; i++)
#pragma unroll
                    for (int j = 0; j < 4; j++)
                        acc_mad(acc[i][j + 4], __popc(xs[kk][i] ^ ws[j]), one);
            }
        }
    }

    // ---- epilogue: u = 2304 - 2*D + border correction ----
    int pcat[4];
#pragma unroll
    for (int i = 0; i < 4; i++) {
        int p = p0 + pg * 4 + i;
        int hw = p % HWs;
        int h = hw / WW, w = hw - h * WW;
        int ht = (h == 0) ? 0 : ((h == HH - 1) ? 2 : 1);
        int wt = (w == 0) ? 0 : ((w == WW - 1) ? 2 : 1);
        pcat[i] = ht * 3 + wt;
    }
    int u[4][8];
#pragma unroll
    for (int j = 0; j < 8; j++) {
        int c = n0 + cg * 8 + j;
#pragma unroll
        for (int i = 0; i < 4; i++) {
            int corr = (pcat[i] == 4) ? 0 : g_corr[pcat[i] * CC + c];
            u[i][j] = KBITS - 2 * acc[i][j] + corr;
        }
    }

    // ---- fused exact BN statistics (integer, order-independent) ----
#pragma unroll
    for (int j = 0; j < 8; j++) {
        int s = 0, s2 = 0;
#pragma unroll
        for (int i = 0; i < 4; i++) { s += u[i][j]; s2 += u[i][j] * u[i][j]; }
#pragma unroll
        for (int m = 1; m < 16; m <<= 1) {
            s  += __shfl_xor_sync(~0u, s, m);
            s2 += __shfl_xor_sync(~0u, s2, m);
        }
        if ((lane & 15) == 0) {
            int c = n0 + cg * 8 + j;
            atomicAdd(&g_isum[c],   (unsigned long long)(long long)s);
            atomicAdd(&g_isumsq[c], (unsigned long long)(long long)s2);
        }
    }

    // ---- store int16 conv result, NCHW ----
    {
        int p2 = p0 + pg * 4;
        int b2 = p2 / HWs, hw2 = p2 - b2 * HWs;
        short* yd = g_y16 + (size_t)b2 * CHW + hw2;
#pragma unroll
        for (int j = 0; j < 8; j++) {
            int c = n0 + cg * 8 + j;
            uint2 val;
            val.x = (uint32_t)(u[0][j] & 0xffff) | ((uint32_t)u[1][j] << 16);
            val.y = (uint32_t)(u[2][j] & 0xffff) | ((uint32_t)u[3][j] << 16);
            *(uint2*)&yd[(size_t)c * HWs] = val;
        }
    }
}

// ---------------------------------------------------------------------------
// Kernel: BN affine coefficients (exact integer stats, weight scale folded)
// ---------------------------------------------------------------------------
__global__ void coeff_kernel(const float* __restrict__ gamma, const float* __restrict__ beta) {
    int c = threadIdx.x;
    double n  = (double)PIX;
    double mu = (double)(long long)g_isum[c] / n;
    double vu = (double)(long long)g_isumsq[c] / n - mu * mu;
    double sc = (double)g_scale[c];
    double A  = (double)gamma[c] * sc / sqrt(sc * sc * vu + (double)BN_EPS);
    g_ab[c]      = (float)A;
    g_ab[CC + c] = (float)((double)beta[c] - A * mu);
}

// ---------------------------------------------------------------------------
// Kernel: out = relu(A*u + B), int16 -> fp32, NCHW
// ---------------------------------------------------------------------------
__global__ void finalize_kernel(float* __restrict__ out) {
    size_t idx = (size_t)blockIdx.x * 256 + threadIdx.x;   // one per 8 elems
    size_t j = idx * 8;
    int c = (int)((j / HWs) & 255);
    float A = g_ab[c], Bv = g_ab[CC + c];
    uint4 raw = ((const uint4*)g_y16)[idx];
    float4 o0, o1;
    o0.x = fmaxf(fmaf((float)(short)(raw.x & 0xffff), A, Bv), 0.0f);
    o0.y = fmaxf(fmaf((float)(short)(raw.x >> 16),    A, Bv), 0.0f);
    o0.z = fmaxf(fmaf((float)(short)(raw.y & 0xffff), A, Bv), 0.0f);
    o0.w = fmaxf(fmaf((float)(short)(raw.y >> 16),    A, Bv), 0.0f);
    o1.x = fmaxf(fmaf((float)(short)(raw.z & 0xffff), A, Bv), 0.0f);
    o1.y = fmaxf(fmaf((float)(short)(raw.z >> 16),    A, Bv), 0.0f);
    o1.z = fmaxf(fmaf((float)(short)(raw.w & 0xffff), A, Bv), 0.0f);
    o1.w = fmaxf(fmaf((float)(short)(raw.w >> 16),    A, Bv), 0.0f);
    ((float4*)out)[idx * 2]     = o0;
    ((float4*)out)[idx * 2 + 1] = o1;
}

// ---------------------------------------------------------------------------
// Launch (gemm is launch index 3 so the profiler lands on it)
// ---------------------------------------------------------------------------
extern "C" void kernel_launch(void* const* d_in, const int* in_sizes, int n_in,
                              void* d_out, int out_size) {
    (void)in_sizes; (void)n_in; (void)out_size;
    const float* x     = (const float*)d_in[0];
    const float* wt    = (const float*)d_in[1];
    const float* gamma = (const float*)d_in[2];
    const float* beta  = (const float*)d_in[3];
    float* out = (float*)d_out;

    static int smem_set = 0;
    if (!smem_set) {
        cudaFuncSetAttribute(gemm_kernel, cudaFuncAttributeMaxDynamicSharedMemorySize,
                             SMEM_DYN);
        smem_set = 1;
    }

    wprep_kernel<<<256, 256>>>(wt);
    zero_xp_kernel<<<(BB * HP * WP * 8 / 4) / 256, 256>>>();
    xpack_kernel<<<dim3(HH, BB), 256>>>(x);
    gemm_kernel<<<dim3(NT_M, 2), 256, SMEM_DYN>>>();
    coeff_kernel<<<1, 256>>>(gamma, beta);
    finalize_kernel<<<(int)((size_t)PIX * CC / 8 / 256), 256>>>(out);
}